// round 1
// baseline (speedup 1.0000x reference)
#include <cuda_runtime.h>

#define B_    32
#define NS_   500
#define D_    1024
#define KSEL  16
#define WARPS 8
#define CAP   128
#define SIGMA_ 0.05f
#define INVN  (1.0f/500.0f)
#define FULLM 0xFFFFFFFFu

// Packed sort key: monotone-mapped float in high 32 bits, (1023-idx) in low bits.
// max() over keys == "larger value wins; among equal values, lower index wins".
// Identity 0 is below any real key (no NaNs in this workload).
__device__ __forceinline__ unsigned long long packkey(float v, int d) {
    unsigned u = __float_as_uint(v);
    u = (u & 0x80000000u) ? ~u : (u | 0x80000000u);
    return ((unsigned long long)u << 32) | (unsigned)(1023 - d);
}

__device__ __forceinline__ unsigned buildmask(const float* v, float T) {
    unsigned m = 0;
#pragma unroll
    for (int s = 0; s < 32; s++) m |= (v[s] >= T) ? (1u << s) : 0u;
    return m;
}

__constant__ float c_ladder[12] = {2.05f, 1.95f, 1.85f, 1.75f, 1.65f, 1.50f,
                                   1.30f, 1.00f, 0.50f, -0.50f, -2.0f, -3.0e38f};

__global__ __launch_bounds__(WARPS * 32)
void ptk_main(const float* __restrict__ x, const float* __restrict__ noise,
              float* __restrict__ out) {
    __shared__ unsigned long long cand[WARPS][CAP];
    const int warp = threadIdx.x >> 5;
    const int lane = threadIdx.x & 31;
    const int row  = blockIdx.x * WARPS + warp;      // row = b*NS_ + n
    const int b    = row / NS_;

    const float4* xr = reinterpret_cast<const float4*>(x + (size_t)b * D_);
    const float4* nr = reinterpret_cast<const float4*>(noise + (size_t)row * D_);

    // Load row: slot s=4j+c holds element d = 128j + 4*lane + c (coalesced float4).
    // __fmul_rn/__fadd_rn: guaranteed-unfused, matches reference mul-then-add rounding.
    float v[32];
#pragma unroll
    for (int j = 0; j < 8; j++) {
        float4 xv = __ldg(&xr[j * 32 + lane]);
        float4 nv = __ldg(&nr[j * 32 + lane]);
        v[4 * j + 0] = __fadd_rn(xv.x, __fmul_rn(nv.x, SIGMA_));
        v[4 * j + 1] = __fadd_rn(xv.y, __fmul_rn(nv.y, SIGMA_));
        v[4 * j + 2] = __fadd_rn(xv.z, __fmul_rn(nv.z, SIGMA_));
        v[4 * j + 3] = __fadd_rn(xv.w, __fmul_rn(nv.w, SIGMA_));
    }

    // --- Threshold probe: descend ladder until >=16 candidates survive ---
    float Thi = 1e30f, T;
    unsigned mask;
    int cnt;
#pragma unroll 1
    for (int li = 0;; li++) {
        T    = c_ladder[li];
        mask = buildmask(v, T);
        cnt  = (int)__reduce_add_sync(FULLM, (unsigned)__popc(mask));
        if (cnt >= KSEL) break;
        Thi = T;
    }
    // Safety net (unreachable with Gaussian data): bisect so cnt <= CAP.
#pragma unroll 1
    for (int g = 0; cnt > CAP && g < 128; g++) {
        float mid = 0.5f * (Thi + T);
        if (!(mid > T && mid < Thi)) break;
        unsigned m2 = buildmask(v, mid);
        int c2 = (int)__reduce_add_sync(FULLM, (unsigned)__popc(m2));
        if (c2 >= KSEL) { T = mid; mask = m2; cnt = c2; }
        else            { Thi = mid; }
    }
    if (cnt > CAP) cnt = CAP;  // clamp (unreachable)

    // --- Compact surviving candidates into the warp's smem slab ---
    int lc  = __popc(mask);
    int off = lc;
#pragma unroll
    for (int s = 1; s < 32; s <<= 1) {
        int o = __shfl_up_sync(FULLM, off, s);
        if (lane >= s) off += o;
    }
    off -= lc;  // exclusive prefix
    unsigned long long* cw = cand[warp];
#pragma unroll
    for (int s = 0; s < 32; s++) {
        if (mask & (1u << s)) {
            int d = ((s >> 2) << 7) + (lane << 2) + (s & 3);
            if (off < CAP) cw[off] = packkey(v[s], d);
            off++;
        }
    }
    __syncwarp();

    int myidx = 0;  // lane k (k<16) ends holding the k-th largest candidate's index
    if (cnt <= 32) {
        // Fast path: warp bitonic sort, descending. Lanes 0..15 -> top-16.
        unsigned long long p = (lane < cnt) ? cw[lane] : 0ull;
#pragma unroll
        for (int k = 2; k <= 32; k <<= 1) {
#pragma unroll
            for (int j = k >> 1; j > 0; j >>= 1) {
                unsigned long long o = __shfl_xor_sync(FULLM, p, j);
                bool keepmax = (((lane & k) == 0) == ((lane & j) == 0));
                unsigned long long mn = p < o ? p : o;
                unsigned long long mx = p < o ? o : p;
                p = keepmax ? mx : mn;
            }
        }
        myidx = 1023 - (int)(unsigned)(p & 0xFFFFFFFFull);
    } else {
        // Slow path (rare): 16 iterative warp-max reductions over <=128 candidates.
        unsigned long long c0 = (lane      < cnt) ? cw[lane]      : 0ull;
        unsigned long long c1 = (lane + 32 < cnt) ? cw[lane + 32] : 0ull;
        unsigned long long c2 = (lane + 64 < cnt) ? cw[lane + 64] : 0ull;
        unsigned long long c3 = (lane + 96 < cnt) ? cw[lane + 96] : 0ull;
#pragma unroll
        for (int k = 0; k < KSEL; k++) {
            unsigned long long best = c0 > c1 ? c0 : c1;
            unsigned long long b2   = c2 > c3 ? c2 : c3;
            best = best > b2 ? best : b2;
#pragma unroll
            for (int j = 16; j > 0; j >>= 1) {
                unsigned long long o = __shfl_xor_sync(FULLM, best, j);
                best = o > best ? o : best;
            }
            if (lane == k) myidx = 1023 - (int)(unsigned)(best & 0xFFFFFFFFull);
            c0 = (c0 == best) ? 0ull : c0;
            c1 = (c1 == best) ? 0ull : c1;
            c2 = (c2 == best) ? 0ull : c2;
            c3 = (c3 == best) ? 0ull : c3;
        }
    }

    // --- Rank the 16 selected indices ascending; scatter-add 1/N ---
    int rank = 0;
#pragma unroll
    for (int i = 0; i < KSEL; i++) {
        int oi = __shfl_sync(FULLM, myidx, i);
        rank += (oi < myidx) ? 1 : 0;
    }
    if (lane < KSEL) {
        atomicAdd(out + ((size_t)b * KSEL + rank) * D_ + myidx, INVN);
    }
}

__global__ void ptk_zero(float4* __restrict__ out) {
    int i = blockIdx.x * blockDim.x + threadIdx.x;
    out[i] = make_float4(0.f, 0.f, 0.f, 0.f);
}

extern "C" void kernel_launch(void* const* d_in, const int* in_sizes, int n_in,
                              void* d_out, int out_size) {
    const float* x     = (const float*)d_in[0];
    const float* noise = (const float*)d_in[1];
    if (n_in >= 2 && in_sizes[0] > in_sizes[1]) {  // defensive: x is the small input
        const float* t = x; x = noise; noise = t;
    }
    float* out = (float*)d_out;

    // (B_*KSEL*D_) floats = 524288 = 131072 float4 = 512 blocks * 256 threads
    ptk_zero<<<512, 256>>>((float4*)out);
    ptk_main<<<(B_ * NS_) / WARPS, WARPS * 32>>>(x, noise, out);
}

// round 2
// speedup vs baseline: 1.0028x; 1.0028x over previous
#include <cuda_runtime.h>

#define B_     32
#define NS_    500
#define D_     1024
#define KSEL   16
#define SIGMA_ 0.05f
#define INVN   (1.0f/500.0f)
#define FULLM  0xFFFFFFFFu

#define MAXC   288          // candidate cap per batch row (typ ~127)
#define SMAX   9            // MAXC/32 register slots per lane
#define MWARPS 4            // main kernel warps/block; 125 blocks per b
#define PRECAP 128          // pre-kernel compaction slab

// ---- per-batch candidate tables (filled by ptk_pre) ----
__device__ unsigned short g_dlist[B_][MAXC];
__device__ float          g_xlist[B_][MAXC];
__device__ int            g_m[B_];
__device__ float          g_x16[B_];

// Packed sort key: monotone-mapped float in high 32 bits, (1023-idx) low.
// max() == "larger value wins; equal value -> lower index wins". 0 < any real key.
__device__ __forceinline__ unsigned long long packkey(float v, int d) {
    unsigned u = __float_as_uint(v);
    u = (u & 0x80000000u) ? ~u : (u | 0x80000000u);
    return ((unsigned long long)u << 32) | (unsigned)(1023 - d);
}

__constant__ float c_ladder[12] = {2.05f, 1.95f, 1.85f, 1.75f, 1.65f, 1.50f,
                                   1.30f, 1.00f, 0.50f, -0.50f, -2.0f, -3.0e38f};
__constant__ float c_off[5] = {-0.10f, -0.22f, -0.38f, -0.60f, -1.0e37f};

// ============ pre-kernel: exact x16 per b + candidate list ============
__global__ __launch_bounds__(32)
void ptk_pre(const float* __restrict__ x) {
    __shared__ unsigned long long cand[PRECAP];
    const int lane = threadIdx.x;
    const int b    = blockIdx.x;
    const float* xr = x + (size_t)b * D_;

    float v[32];                       // slot j holds d = 32*j + lane
#pragma unroll
    for (int j = 0; j < 32; j++) v[j] = xr[32 * j + lane];

    // ladder probe (proven R1 machinery)
    float Thi = 1e30f, T;
    unsigned mask;
    int cnt;
#pragma unroll 1
    for (int li = 0;; li++) {
        T = c_ladder[li];
        unsigned m2 = 0;
#pragma unroll
        for (int s = 0; s < 32; s++) m2 |= (v[s] >= T) ? (1u << s) : 0u;
        mask = m2;
        cnt  = (int)__reduce_add_sync(FULLM, (unsigned)__popc(mask));
        if (cnt >= KSEL) break;
        Thi = T;
    }
#pragma unroll 1
    for (int g = 0; cnt > PRECAP && g < 128; g++) {   // unreachable safety
        float mid = 0.5f * (Thi + T);
        if (!(mid > T && mid < Thi)) break;
        unsigned m2 = 0;
#pragma unroll
        for (int s = 0; s < 32; s++) m2 |= (v[s] >= mid) ? (1u << s) : 0u;
        int c2 = (int)__reduce_add_sync(FULLM, (unsigned)__popc(m2));
        if (c2 >= KSEL) { T = mid; mask = m2; cnt = c2; }
        else            { Thi = mid; }
    }
    if (cnt > PRECAP) cnt = PRECAP;

    // compact
    int lc = __popc(mask), off = lc;
#pragma unroll
    for (int s = 1; s < 32; s <<= 1) {
        int o = __shfl_up_sync(FULLM, off, s);
        if (lane >= s) off += o;
    }
    off -= lc;
#pragma unroll
    for (int s = 0; s < 32; s++) {
        if (mask & (1u << s)) {
            if (off < PRECAP) cand[off] = packkey(v[s], 32 * s + lane);
            off++;
        }
    }
    __syncwarp();

    int myidx = 0;
    if (cnt <= 32) {
        unsigned long long p = (lane < cnt) ? cand[lane] : 0ull;
#pragma unroll
        for (int k = 2; k <= 32; k <<= 1) {
#pragma unroll
            for (int j = k >> 1; j > 0; j >>= 1) {
                unsigned long long o = __shfl_xor_sync(FULLM, p, j);
                bool keepmax = (((lane & k) == 0) == ((lane & j) == 0));
                unsigned long long mn = p < o ? p : o;
                unsigned long long mx = p < o ? o : p;
                p = keepmax ? mx : mn;
            }
        }
        myidx = 1023 - (int)(unsigned)(p & 0xFFFFFFFFull);
    } else {
        unsigned long long c0 = (lane      < cnt) ? cand[lane]      : 0ull;
        unsigned long long c1 = (lane + 32 < cnt) ? cand[lane + 32] : 0ull;
        unsigned long long c2 = (lane + 64 < cnt) ? cand[lane + 64] : 0ull;
        unsigned long long c3 = (lane + 96 < cnt) ? cand[lane + 96] : 0ull;
#pragma unroll
        for (int k = 0; k < KSEL; k++) {
            unsigned long long best = c0 > c1 ? c0 : c1;
            unsigned long long b2   = c2 > c3 ? c2 : c3;
            best = best > b2 ? best : b2;
#pragma unroll
            for (int j = 16; j > 0; j >>= 1) {
                unsigned long long o = __shfl_xor_sync(FULLM, best, j);
                best = o > best ? o : best;
            }
            if (lane == k) myidx = 1023 - (int)(unsigned)(best & 0xFFFFFFFFull);
            c0 = (c0 == best) ? 0ull : c0;
            c1 = (c1 == best) ? 0ull : c1;
            c2 = (c2 == best) ? 0ull : c2;
            c3 = (c3 == best) ? 0ull : c3;
        }
    }

    int idx16 = __shfl_sync(FULLM, myidx, KSEL - 1);
    float x16 = xr[idx16];

    // candidate threshold with 1.0 margin (>=20-sigma combined noise to violate)
    float Tx = x16 - 1.0f;
    int total;
#pragma unroll 1
    for (;;) {
        int c = 0;
#pragma unroll
        for (int j = 0; j < 32; j++) c += (v[j] >= Tx) ? 1 : 0;
        total = (int)__reduce_add_sync(FULLM, (unsigned)c);
        if (total <= MAXC) break;
        Tx += 0.1f;                    // unreachable with Gaussian data
    }

    // write candidate list in ascending d
    int base = 0;
#pragma unroll 1
    for (int j = 0; j < 32; j++) {
        bool sel = (v[j] >= Tx);
        unsigned bal = __ballot_sync(FULLM, sel);
        if (sel) {
            int pos = base + __popc(bal & ((1u << lane) - 1u));
            g_dlist[b][pos] = (unsigned short)(32 * j + lane);
            g_xlist[b][pos] = v[j];
        }
        base += __popc(bal);
    }
    if (lane == 0) { g_m[b] = total; g_x16[b] = x16; }
}

// ============ main kernel: one warp per (b, sample) over candidates ============
__global__ __launch_bounds__(MWARPS * 32)
void ptk_sel(const float* __restrict__ noise, float* __restrict__ out) {
    __shared__ unsigned short sd[MAXC];
    __shared__ float          sx[MAXC];
    __shared__ unsigned long long slab[MWARPS][32];
    __shared__ float s_x16;
    __shared__ int   s_m;

    const int tid  = threadIdx.x;
    const int lane = tid & 31;
    const int warp = tid >> 5;
    const int b    = blockIdx.x / 125;
    const int row  = b * NS_ + (blockIdx.x % 125) * MWARPS + warp;

    if (tid == 0) { s_m = g_m[b]; s_x16 = g_x16[b]; }
    for (int i = tid; i < MAXC; i += MWARPS * 32) {
        sd[i] = g_dlist[b][i];
        sx[i] = g_xlist[b][i];
    }
    __syncthreads();

    const int   m   = s_m;
    const float x16 = s_x16;
    const float* nr = noise + (size_t)row * D_;

    // gather candidates: slot j holds candidate c = 32*j + lane (ascending d)
    float vv[SMAX];
#pragma unroll
    for (int j = 0; j < SMAX; j++) {
        int c = 32 * j + lane;
        if (c < m)
            vv[j] = __fadd_rn(sx[c], __fmul_rn(__ldg(nr + sd[c]), SIGMA_));
        else
            vv[j] = -3.0e38f;
    }

    // x16-relative ladder; final rung admits all m (>=16) candidates
    float T;
    unsigned mask;
    int cnt;
#pragma unroll 1
    for (int li = 0;; li++) {
        T = x16 + c_off[li];
        unsigned m2 = 0;
#pragma unroll
        for (int j = 0; j < SMAX; j++) m2 |= (vv[j] >= T) ? (1u << j) : 0u;
        mask = m2;
        cnt  = (int)__reduce_add_sync(FULLM, (unsigned)__popc(mask));
        if (cnt >= KSEL) break;
    }

    int myidx = 0;
    if (cnt <= 32) {
        // compact -> warp slab -> 32-wide bitonic (descending); lanes 0..15 = top-16
        int lc = __popc(mask), off = lc;
#pragma unroll
        for (int s = 1; s < 32; s <<= 1) {
            int o = __shfl_up_sync(FULLM, off, s);
            if (lane >= s) off += o;
        }
        off -= lc;
#pragma unroll
        for (int j = 0; j < SMAX; j++) {
            if (mask & (1u << j)) {
                int d = sd[32 * j + lane];
                slab[warp][off] = packkey(vv[j], d);
                off++;
            }
        }
        __syncwarp();
        unsigned long long p = (lane < cnt) ? slab[warp][lane] : 0ull;
#pragma unroll
        for (int k = 2; k <= 32; k <<= 1) {
#pragma unroll
            for (int j = k >> 1; j > 0; j >>= 1) {
                unsigned long long o = __shfl_xor_sync(FULLM, p, j);
                bool keepmax = (((lane & k) == 0) == ((lane & j) == 0));
                unsigned long long mn = p < o ? p : o;
                unsigned long long mx = p < o ? o : p;
                p = keepmax ? mx : mn;
            }
        }
        myidx = 1023 - (int)(unsigned)(p & 0xFFFFFFFFull);
    } else {
        // rare: iterative 16x max-reduce over register slots (handles any cnt<=m)
        unsigned long long kk[SMAX];
#pragma unroll
        for (int j = 0; j < SMAX; j++) {
            int c = 32 * j + lane;
            kk[j] = ((mask >> j) & 1u) ? packkey(vv[j], sd[c]) : 0ull;
        }
#pragma unroll 1
        for (int k = 0; k < KSEL; k++) {
            unsigned long long best = kk[0];
#pragma unroll
            for (int j = 1; j < SMAX; j++) best = kk[j] > best ? kk[j] : best;
#pragma unroll
            for (int s = 16; s > 0; s >>= 1) {
                unsigned long long o = __shfl_xor_sync(FULLM, best, s);
                best = o > best ? o : best;
            }
            if (lane == k) myidx = 1023 - (int)(unsigned)(best & 0xFFFFFFFFull);
#pragma unroll
            for (int j = 0; j < SMAX; j++) if (kk[j] == best) kk[j] = 0ull;
        }
    }

    // rank selected indices ascending; scatter-add 1/N
    int rank = 0;
#pragma unroll
    for (int i = 0; i < KSEL; i++) {
        int oi = __shfl_sync(FULLM, myidx, i);
        rank += (oi < myidx) ? 1 : 0;
    }
    if (lane < KSEL) {
        atomicAdd(out + ((size_t)b * KSEL + rank) * D_ + myidx, INVN);
    }
}

__global__ void ptk_zero(float4* __restrict__ out) {
    int i = blockIdx.x * blockDim.x + threadIdx.x;
    out[i] = make_float4(0.f, 0.f, 0.f, 0.f);
}

extern "C" void kernel_launch(void* const* d_in, const int* in_sizes, int n_in,
                              void* d_out, int out_size) {
    const float* x     = (const float*)d_in[0];
    const float* noise = (const float*)d_in[1];
    if (n_in >= 2 && in_sizes[0] > in_sizes[1]) {   // defensive: x is the small input
        const float* t = x; x = noise; noise = t;
    }
    float* out = (float*)d_out;

    ptk_zero<<<512, 256>>>((float4*)out);          // 524288 floats
    ptk_pre<<<B_, 32>>>(x);
    ptk_sel<<<B_ * 125, MWARPS * 32>>>(noise, out);
}

// round 3
// speedup vs baseline: 1.0875x; 1.0845x over previous
#include <cuda_runtime.h>

#define B_     32
#define NS_    500
#define D_     1024
#define KSEL   16
#define SIGMA_ 0.05f
#define INVN   (1.0f/500.0f)
#define FULLM  0xFFFFFFFFu

#define MARGIN 0.8f         // >=16-sigma combined noise needed to violate
#define MAXC   160          // candidate cap per batch row (typ ~104)
#define SMAX   5            // MAXC/32 register slots per lane
#define MWARPS 4            // sel warps/block; 125 blocks per b
#define PRECAP 128          // pre compaction slab
#define ZBLK   512          // zeroing blocks in the fused init kernel

// ---- per-batch candidate tables (filled by init's pre warps) ----
__device__ unsigned short g_dlist[B_][MAXC];
__device__ float          g_xlist[B_][MAXC];
__device__ int            g_m[B_];
__device__ float          g_x16[B_];

// Packed sort key: monotone-mapped float in high 32 bits, (1023-idx) low.
// max() == "larger value wins; equal value -> lower index wins". 0 < any real key.
__device__ __forceinline__ unsigned long long packkey(float v, int d) {
    unsigned u = __float_as_uint(v);
    u = (u & 0x80000000u) ? ~u : (u | 0x80000000u);
    return ((unsigned long long)u << 32) | (unsigned)(1023 - d);
}

__constant__ float c_ladder[12] = {2.05f, 1.95f, 1.85f, 1.75f, 1.65f, 1.50f,
                                   1.30f, 1.00f, 0.50f, -0.50f, -2.0f, -3.0e38f};
__constant__ float c_off[5] = {-0.08f, -0.18f, -0.32f, -0.55f, -(MARGIN)};

// ============ fused init: blocks [0,ZBLK) zero out; blocks [ZBLK,ZBLK+4) run pre ============
__global__ __launch_bounds__(256)
void ptk_init(const float* __restrict__ x, float4* __restrict__ out4) {
    if (blockIdx.x < ZBLK) {
        out4[blockIdx.x * 256 + threadIdx.x] = make_float4(0.f, 0.f, 0.f, 0.f);
        return;
    }
    __shared__ unsigned long long cand[8][PRECAP];
    const int lane = threadIdx.x & 31;
    const int w    = threadIdx.x >> 5;
    const int b    = (blockIdx.x - ZBLK) * 8 + w;      // 4 blocks x 8 warps = 32 b
    const float* xr = x + (size_t)b * D_;
    unsigned long long* cw = cand[w];

    float v[32];                       // slot j holds d = 32*j + lane (coalesced)
#pragma unroll
    for (int j = 0; j < 32; j++) v[j] = xr[32 * j + lane];

    // absolute ladder probe for exact top-16 of x
    float Thi = 1e30f, T;
    unsigned mask;
    int cnt;
#pragma unroll 1
    for (int li = 0;; li++) {
        T = c_ladder[li];
        unsigned m2 = 0;
#pragma unroll
        for (int s = 0; s < 32; s++) m2 |= (v[s] >= T) ? (1u << s) : 0u;
        mask = m2;
        cnt  = (int)__reduce_add_sync(FULLM, (unsigned)__popc(mask));
        if (cnt >= KSEL) break;
        Thi = T;
    }
#pragma unroll 1
    for (int g = 0; cnt > PRECAP && g < 128; g++) {   // unreachable safety
        float mid = 0.5f * (Thi + T);
        if (!(mid > T && mid < Thi)) break;
        unsigned m2 = 0;
#pragma unroll
        for (int s = 0; s < 32; s++) m2 |= (v[s] >= mid) ? (1u << s) : 0u;
        int c2 = (int)__reduce_add_sync(FULLM, (unsigned)__popc(m2));
        if (c2 >= KSEL) { T = mid; mask = m2; cnt = c2; }
        else            { Thi = mid; }
    }
    if (cnt > PRECAP) cnt = PRECAP;

    // compact survivors
    int lc = __popc(mask), off = lc;
#pragma unroll
    for (int s = 1; s < 32; s <<= 1) {
        int o = __shfl_up_sync(FULLM, off, s);
        if (lane >= s) off += o;
    }
    off -= lc;
#pragma unroll
    for (int s = 0; s < 32; s++) {
        if (mask & (1u << s)) {
            if (off < PRECAP) cw[off] = packkey(v[s], 32 * s + lane);
            off++;
        }
    }
    __syncwarp();

    int myidx = 0;
    if (cnt <= 32) {
        unsigned long long p = (lane < cnt) ? cw[lane] : 0ull;
#pragma unroll
        for (int k = 2; k <= 32; k <<= 1) {
#pragma unroll
            for (int j = k >> 1; j > 0; j >>= 1) {
                unsigned long long o = __shfl_xor_sync(FULLM, p, j);
                bool keepmax = (((lane & k) == 0) == ((lane & j) == 0));
                unsigned long long mn = p < o ? p : o;
                unsigned long long mx = p < o ? o : p;
                p = keepmax ? mx : mn;
            }
        }
        myidx = 1023 - (int)(unsigned)(p & 0xFFFFFFFFull);
    } else {
        unsigned long long c0 = (lane      < cnt) ? cw[lane]      : 0ull;
        unsigned long long c1 = (lane + 32 < cnt) ? cw[lane + 32] : 0ull;
        unsigned long long c2 = (lane + 64 < cnt) ? cw[lane + 64] : 0ull;
        unsigned long long c3 = (lane + 96 < cnt) ? cw[lane + 96] : 0ull;
#pragma unroll
        for (int k = 0; k < KSEL; k++) {
            unsigned long long best = c0 > c1 ? c0 : c1;
            unsigned long long b2   = c2 > c3 ? c2 : c3;
            best = best > b2 ? best : b2;
#pragma unroll
            for (int j = 16; j > 0; j >>= 1) {
                unsigned long long o = __shfl_xor_sync(FULLM, best, j);
                best = o > best ? o : best;
            }
            if (lane == k) myidx = 1023 - (int)(unsigned)(best & 0xFFFFFFFFull);
            c0 = (c0 == best) ? 0ull : c0;
            c1 = (c1 == best) ? 0ull : c1;
            c2 = (c2 == best) ? 0ull : c2;
            c3 = (c3 == best) ? 0ull : c3;
        }
    }

    int idx16 = __shfl_sync(FULLM, myidx, KSEL - 1);
    float x16 = xr[idx16];

    // candidate threshold with MARGIN; raise (unreachable) if list would overflow
    float Tx = x16 - MARGIN;
    int total;
#pragma unroll 1
    for (;;) {
        int c = 0;
#pragma unroll
        for (int j = 0; j < 32; j++) c += (v[j] >= Tx) ? 1 : 0;
        total = (int)__reduce_add_sync(FULLM, (unsigned)c);
        if (total <= MAXC || Tx >= x16 - 0.1f) break;
        Tx += 0.05f;
    }

    // write candidate list in ascending d
    int base = 0;
#pragma unroll 1
    for (int j = 0; j < 32; j++) {
        bool sel = (v[j] >= Tx) && (base < MAXC);
        unsigned bal = __ballot_sync(FULLM, sel);
        if (sel) {
            int pos = base + __popc(bal & ((1u << lane) - 1u));
            if (pos < MAXC) {
                g_dlist[b][pos] = (unsigned short)(32 * j + lane);
                g_xlist[b][pos] = v[j];
            }
        }
        base += __popc(bal);
    }
    if (lane == 0) {
        g_m[b]   = total <= MAXC ? total : MAXC;
        g_x16[b] = x16;
    }
}

// ============ sel: one warp per (b, sample) over <=160 candidates ============
__global__ __launch_bounds__(MWARPS * 32)
void ptk_sel(const float* __restrict__ noise, float* __restrict__ out) {
    __shared__ unsigned short sd[MAXC];
    __shared__ float          sx[MAXC];
    __shared__ unsigned long long slab[MWARPS][32];
    __shared__ float s_x16;
    __shared__ int   s_m;

    const int tid  = threadIdx.x;
    const int lane = tid & 31;
    const int warp = tid >> 5;
    const int b    = blockIdx.x / 125;
    const int row  = b * NS_ + (blockIdx.x % 125) * MWARPS + warp;

    if (tid == 0) { s_m = g_m[b]; s_x16 = g_x16[b]; }
    for (int i = tid; i < MAXC; i += MWARPS * 32) {
        sd[i] = g_dlist[b][i];
        sx[i] = g_xlist[b][i];
    }
    __syncthreads();

    const int   m   = s_m;
    const float x16 = s_x16;
    const float* nr = noise + (size_t)row * D_;

    // gather candidates: slot j holds candidate c = 32*j + lane (ascending d,
    // so each LDG touches ~10 consecutive 128B lines, not 32)
    float vv[SMAX];
#pragma unroll
    for (int j = 0; j < SMAX; j++) {
        int c = 32 * j + lane;
        if (c < m)
            vv[j] = __fadd_rn(sx[c], __fmul_rn(__ldg(nr + sd[c]), SIGMA_));
        else
            vv[j] = -3.0e38f;
    }

    // x16-relative ladder; final rung admits all m (>=16) candidates
    float T;
    unsigned mask;
    int cnt;
#pragma unroll 1
    for (int li = 0;; li++) {
        T = x16 + c_off[li];
        unsigned m2 = 0;
#pragma unroll
        for (int j = 0; j < SMAX; j++) m2 |= (vv[j] >= T) ? (1u << j) : 0u;
        mask = m2;
        cnt  = (int)__reduce_add_sync(FULLM, (unsigned)__popc(mask));
        if (cnt >= KSEL) break;
    }

    int myidx = 0;
    if (cnt <= 32) {
        // compact -> slab -> 32-wide bitonic (descending); lanes 0..15 = top-16
        int lc = __popc(mask), off = lc;
#pragma unroll
        for (int s = 1; s < 32; s <<= 1) {
            int o = __shfl_up_sync(FULLM, off, s);
            if (lane >= s) off += o;
        }
        off -= lc;
#pragma unroll
        for (int j = 0; j < SMAX; j++) {
            if (mask & (1u << j)) {
                int d = sd[32 * j + lane];
                slab[warp][off] = packkey(vv[j], d);
                off++;
            }
        }
        __syncwarp();
        unsigned long long p = (lane < cnt) ? slab[warp][lane] : 0ull;
#pragma unroll
        for (int k = 2; k <= 32; k <<= 1) {
#pragma unroll
            for (int j = k >> 1; j > 0; j >>= 1) {
                unsigned long long o = __shfl_xor_sync(FULLM, p, j);
                bool keepmax = (((lane & k) == 0) == ((lane & j) == 0));
                unsigned long long mn = p < o ? p : o;
                unsigned long long mx = p < o ? o : p;
                p = keepmax ? mx : mn;
            }
        }
        myidx = 1023 - (int)(unsigned)(p & 0xFFFFFFFFull);
    } else {
        // rare: iterative 16x max-reduce over register slots (any cnt<=160)
        unsigned long long kk[SMAX];
#pragma unroll
        for (int j = 0; j < SMAX; j++) {
            int c = 32 * j + lane;
            kk[j] = ((mask >> j) & 1u) ? packkey(vv[j], sd[c]) : 0ull;
        }
#pragma unroll 1
        for (int k = 0; k < KSEL; k++) {
            unsigned long long best = kk[0];
#pragma unroll
            for (int j = 1; j < SMAX; j++) best = kk[j] > best ? kk[j] : best;
#pragma unroll
            for (int s = 16; s > 0; s >>= 1) {
                unsigned long long o = __shfl_xor_sync(FULLM, best, s);
                best = o > best ? o : best;
            }
            if (lane == k) myidx = 1023 - (int)(unsigned)(best & 0xFFFFFFFFull);
#pragma unroll
            for (int j = 0; j < SMAX; j++) if (kk[j] == best) kk[j] = 0ull;
        }
    }

    // rank selected indices ascending; scatter-add 1/N
    int rank = 0;
#pragma unroll
    for (int i = 0; i < KSEL; i++) {
        int oi = __shfl_sync(FULLM, myidx, i);
        rank += (oi < myidx) ? 1 : 0;
    }
    if (lane < KSEL) {
        atomicAdd(out + ((size_t)b * KSEL + rank) * D_ + myidx, INVN);
    }
}

extern "C" void kernel_launch(void* const* d_in, const int* in_sizes, int n_in,
                              void* d_out, int out_size) {
    const float* x     = (const float*)d_in[0];
    const float* noise = (const float*)d_in[1];
    if (n_in >= 2 && in_sizes[0] > in_sizes[1]) {   // defensive: x is the small input
        const float* t = x; x = noise; noise = t;
    }
    float* out = (float*)d_out;

    // ZBLK*256 float4 = 2MB zeroed; 4 extra blocks run the per-b pre stage
    ptk_init<<<ZBLK + 4, 256>>>(x, (float4*)out);
    ptk_sel<<<B_ * 125, MWARPS * 32>>>(noise, out);
}